// round 15
// baseline (speedup 1.0000x reference)
#include <cuda_runtime.h>
#include <math.h>

// Problem constants
#define B    64
#define SEQ  512
#define H    1024
#define OUTD 128

// Fused config: 128 recurrence CTAs + 20 epilogue workers.
#define G    128           // recurrence CTAs (barrier participants)
#define NEP  20            // epilogue worker CTAs (read-only pollers)
#define GT   (G + NEP)     // 148 = SM count -> all co-resident, 1 CTA/SM
#define CPC  8             // columns of W_hh per CTA (H / G)
#define NT   512           // 16 warps -> 4 per SMSP
#define NW   16
#define KW   (H / NW)      // 64 k per warp
#define SLOT 520           // floats per partial slot: 8j*64b + 8 pad (u64-aligned)

static_assert(G * CPC == H, "partition");

typedef unsigned long long u64;

// Scratch (device globals: allocation-free rule). Zero-initialized at load.
__device__ float g_hs[(size_t)SEQ * H * B];  // hidden states [t][h][b]
__device__ float g_h0[H * B];                // initial h = 0 (never written)
__device__ unsigned g_arrive;
__device__ volatile unsigned g_release;

// ---------------------------------------------------------------------------
// Packed f32x2 helpers (Blackwell FFMA2)
// ---------------------------------------------------------------------------
__device__ __forceinline__ void ffma2(u64& d, u64 a, u64 b) {
    asm("fma.rn.f32x2 %0, %1, %2, %3;" : "=l"(d) : "l"(a), "l"(b), "l"(d));
}
__device__ __forceinline__ u64 dup2(float x) {
    u64 r; unsigned u = __float_as_uint(x);
    asm("mov.b64 %0, {%1, %2};" : "=l"(r) : "r"(u), "r"(u));
    return r;
}
__device__ __forceinline__ void unpack2(u64 v, float& x, float& y) {
    unsigned lo, hi;
    asm("mov.b64 {%0, %1}, %2;" : "=r"(lo), "=r"(hi) : "l"(v));
    x = __uint_as_float(lo); y = __uint_as_float(hi);
}

__device__ __forceinline__ float tanh_safe(float x) {
    float ax = fabsf(x);
    float e  = __expf(2.0f * ax);
    float r  = 1.0f - 2.0f / (e + 1.0f);
    return copysignf(r, x);
}

// ---------------------------------------------------------------------------
// Grid barrier among the 128 recurrence CTAs (proven R3/R9/R13). Workers only
// read g_release. Reset kernel zeroes state per launch (graph replays).
// ---------------------------------------------------------------------------
__device__ __forceinline__ void grid_sync() {
    __syncthreads();
    if (threadIdx.x == 0) {
        __threadfence();
        unsigned gen = g_release;
        if (atomicAdd(&g_arrive, 1u) == G - 1u) {
            g_arrive = 0;
            __threadfence();
            g_release = gen + 1u;
        } else {
            while (g_release == gen) { }
        }
        __threadfence();
    }
    __syncthreads();
}

__global__ void rnn_reset_kernel() {
    if (threadIdx.x == 0) { g_arrive = 0u; *(unsigned*)&g_release = 0u; }
}

// ---------------------------------------------------------------------------
// Fused persistent kernel.
//  bid < G : recurrence. h_t = tanh(h_{t-1}@W_hh + W_xh[X[:,t]] + b_h).
//    CTA owns columns [c0, c0+8). W pre-duplicated in smem as (w,w) u64 pairs
//    -> inner loop: LDS broadcasts (N=1) + LDG.64 h pairs + FFMA2 only.
//    Lane l of warp w: batches (2l, 2l+1), k-range [64w, 64w+64), all 8 cols.
//  bid >= G: epilogue worker (R13-proven body, split-k 512 threads).
// ---------------------------------------------------------------------------
__global__ void __launch_bounds__(NT, 1)
rnn_fused_kernel(const int* __restrict__ X,
                 const float* __restrict__ W_hh,
                 const float* __restrict__ W_xh,
                 const float* __restrict__ W_hy,
                 const float* __restrict__ b_h,
                 const float* __restrict__ b_y,
                 float* __restrict__ out) {
    extern __shared__ float sm[];
    const int tid = threadIdx.x;
    const int bid = blockIdx.x;

    if (bid < G) {
        // ================= recurrence role =================
        u64*   wd  = (u64*)sm;            // [H][8] duplicated W pairs, 64 KB
        float* red = sm + 16384;          // [16][520] partials, ~33 KB

        const int c0 = bid * CPC;

        // One-time W_hh slice load, duplicated: wd[k*8+j] = (W[k][c0+j]) x2
        for (int i = tid; i < H * CPC; i += NT) {
            int k = i >> 3, j = i & 7;
            float v = W_hh[(size_t)k * H + c0 + j];
            float2 p; p.x = v; p.y = v;
            ((float2*)wd)[i] = p;
        }

        const int w    = tid >> 5;
        const int lane = tid & 31;
        const int bl   = lane * 2;        // this lane's batch pair
        float* rst = red + w * SLOT;      // warp slot base; acc[j] -> rst+j*64+bl

        const int jr = tid >> 6;          // 0..7
        const int br = tid & 63;
        const float bh = b_h[c0 + jr];

        __syncthreads();

        for (int t = 0; t < SEQ; t++) {
            const float* hp = t ? (g_hs + (size_t)(t - 1) * H * B) : g_h0;

            // Early-issue token + W_xh gather (retires under GEMM)
            int   tk = X[br * SEQ + t];
            float wx = W_xh[(size_t)tk * H + c0 + jr];

            u64 acc[8];
            #pragma unroll
            for (int j = 0; j < 8; j++) acc[j] = 0ull;

            const float* hb = hp + (size_t)(w * KW) * B + bl;
            const u64*   wb = wd + (w * KW) * 8;

            #pragma unroll 8
            for (int kk = 0; kk < KW; kk++) {
                u64 hreg = *(const u64*)(hb + (size_t)kk * B);         // (b, b+1)
                ulonglong2 p0 = *(const ulonglong2*)(wb + kk * 8);     // j0,j1
                ulonglong2 p1 = *(const ulonglong2*)(wb + kk * 8 + 2); // j2,j3
                ulonglong2 p2 = *(const ulonglong2*)(wb + kk * 8 + 4); // j4,j5
                ulonglong2 p3 = *(const ulonglong2*)(wb + kk * 8 + 6); // j6,j7
                ffma2(acc[0], hreg, p0.x); ffma2(acc[1], hreg, p0.y);
                ffma2(acc[2], hreg, p1.x); ffma2(acc[3], hreg, p1.y);
                ffma2(acc[4], hreg, p2.x); ffma2(acc[5], hreg, p2.y);
                ffma2(acc[6], hreg, p3.x); ffma2(acc[7], hreg, p3.y);
            }

            // Stash: red[w][j][b] — 8B-aligned u64 stores (bl even)
            #pragma unroll
            for (int j = 0; j < 8; j++)
                *(u64*)(rst + j * 64 + bl) = acc[j];
            __syncthreads();

            // Reduce 16 slots + input proj + bias + tanh; write h_t [h][b].
            {
                const float* rb = red + jr * 64 + br;
                float s0 = 0.f, s1 = 0.f, s2 = 0.f, s3 = 0.f;
                #pragma unroll
                for (int sl = 0; sl < NW; sl += 4) {
                    s0 += rb[(sl + 0) * SLOT];
                    s1 += rb[(sl + 1) * SLOT];
                    s2 += rb[(sl + 2) * SLOT];
                    s3 += rb[(sl + 3) * SLOT];
                }
                float x = ((s0 + s1) + (s2 + s3)) + wx + bh;
                g_hs[(size_t)t * H * B + (size_t)(c0 + jr) * B + br] = tanh_safe(x);
            }

            grid_sync();
        }
    } else {
        // ================= epilogue worker role (R13 verbatim) =================
        float* hc = sm;             // [k64][b64]  16 KB
        float* Wc = sm + 64 * 64;   // [k64][o128] 32 KB

        const int tl = tid & 255;          // tile lane: pair (tl, tl+256)
        const int b0 = (tl & 15) * 4;
        const int o0 = (tl >> 4) * 8;
        const int kh = (tid >> 8) * 32;    // k-half: 0 or 32

        float byv[8];
        #pragma unroll
        for (int oi = 0; oi < 8; oi++) byv[oi] = b_y[o0 + oi];

        for (int t = bid - G; t < SEQ; t += NEP) {
            if (tid == 0) {
                while (g_release < (unsigned)(t + 1)) __nanosleep(128);
                __threadfence();
            }
            __syncthreads();

            u64 acc[4][4];
            #pragma unroll
            for (int bi = 0; bi < 4; bi++)
                #pragma unroll
                for (int op = 0; op < 4; op++) acc[bi][op] = 0ull;

            const float* hsrc = g_hs + (size_t)t * H * B;

            for (int k0 = 0; k0 < H; k0 += 64) {
                const float4* hsv = (const float4*)(hsrc + (size_t)k0 * B);
                float4* hcv = (float4*)hc;
                #pragma unroll
                for (int i = 0; i < 2; i++) hcv[tid + i * 512] = hsv[tid + i * 512];

                const float4* wsv = (const float4*)(W_hy + (size_t)k0 * OUTD);
                float4* wcv = (float4*)Wc;
                #pragma unroll
                for (int i = 0; i < 4; i++) wcv[tid + i * 512] = wsv[tid + i * 512];

                __syncthreads();

                #pragma unroll 4
                for (int kk = 0; kk < 32; kk++) {
                    int k = kh + kk;
                    float4 hv = *(const float4*)(hc + k * 64 + b0);
                    ulonglong2 wq0 = *(const ulonglong2*)(Wc + k * OUTD + o0);
                    ulonglong2 wq1 = *(const ulonglong2*)(Wc + k * OUTD + o0 + 4);
                    u64 h0 = dup2(hv.x), h1 = dup2(hv.y), h2 = dup2(hv.z), h3 = dup2(hv.w);
                    ffma2(acc[0][0], h0, wq0.x); ffma2(acc[0][1], h0, wq0.y);
                    ffma2(acc[0][2], h0, wq1.x); ffma2(acc[0][3], h0, wq1.y);
                    ffma2(acc[1][0], h1, wq0.x); ffma2(acc[1][1], h1, wq0.y);
                    ffma2(acc[1][2], h1, wq1.x); ffma2(acc[1][3], h1, wq1.y);
                    ffma2(acc[2][0], h2, wq0.x); ffma2(acc[2][1], h2, wq0.y);
                    ffma2(acc[2][2], h2, wq1.x); ffma2(acc[2][3], h2, wq1.y);
                    ffma2(acc[3][0], h3, wq0.x); ffma2(acc[3][1], h3, wq0.y);
                    ffma2(acc[3][2], h3, wq1.x); ffma2(acc[3][3], h3, wq1.y);
                }
                __syncthreads();
            }

            {
                float* stage = hc;
                if (tid >= 256) {
                    float* dstp = stage + tl * 33;
                    #pragma unroll
                    for (int bi = 0; bi < 4; bi++) {
                        float f[8];
                        unpack2(acc[bi][0], f[0], f[1]);
                        unpack2(acc[bi][1], f[2], f[3]);
                        unpack2(acc[bi][2], f[4], f[5]);
                        unpack2(acc[bi][3], f[6], f[7]);
                        #pragma unroll
                        for (int oi = 0; oi < 8; oi++) dstp[bi * 8 + oi] = f[oi];
                    }
                }
                __syncthreads();
                if (tid < 256) {
                    const float* srcp = stage + tl * 33;
                    #pragma unroll
                    for (int bi = 0; bi < 4; bi++) {
                        float f[8];
                        unpack2(acc[bi][0], f[0], f[1]);
                        unpack2(acc[bi][1], f[2], f[3]);
                        unpack2(acc[bi][2], f[4], f[5]);
                        unpack2(acc[bi][3], f[6], f[7]);
                        float* dst = out + ((size_t)(b0 + bi) * SEQ + t) * OUTD + o0;
                        float4 v0, v1;
                        v0.x = f[0] + srcp[bi*8+0] + byv[0];
                        v0.y = f[1] + srcp[bi*8+1] + byv[1];
                        v0.z = f[2] + srcp[bi*8+2] + byv[2];
                        v0.w = f[3] + srcp[bi*8+3] + byv[3];
                        v1.x = f[4] + srcp[bi*8+4] + byv[4];
                        v1.y = f[5] + srcp[bi*8+5] + byv[5];
                        v1.z = f[6] + srcp[bi*8+6] + byv[6];
                        v1.w = f[7] + srcp[bi*8+7] + byv[7];
                        *(float4*)(dst)     = v0;
                        *(float4*)(dst + 4) = v1;
                    }
                }
                __syncthreads();
            }
        }
    }
}

// ---------------------------------------------------------------------------
// Launch. Inputs: X[i32 64x512], W_hh[f32 1024x1024], W_xh[f32 128x1024],
// W_hy[f32 1024x128], b_h[1024], b_y[128]. Output: f32 [64][512][128].
// ---------------------------------------------------------------------------
extern "C" void kernel_launch(void* const* d_in, const int* in_sizes, int n_in,
                              void* d_out, int out_size) {
    const int*   X    = (const int*)  d_in[0];
    const float* W_hh = (const float*)d_in[1];
    const float* W_xh = (const float*)d_in[2];
    const float* W_hy = (const float*)d_in[3];
    const float* b_h  = (const float*)d_in[4];
    const float* b_y  = (const float*)d_in[5];
    float* out = (float*)d_out;

    const int smem_rec = 16384 * (int)sizeof(float)            // wd (64 KB)
                       + NW * SLOT * (int)sizeof(float);       // red (~33 KB)
    const int smem_epi = (64 * 64 + 64 * OUTD) * (int)sizeof(float);
    const int smem = smem_rec > smem_epi ? smem_rec : smem_epi;

    cudaFuncSetAttribute(rnn_fused_kernel,
                         cudaFuncAttributeMaxDynamicSharedMemorySize, smem);

    rnn_reset_kernel<<<1, 32>>>();
    rnn_fused_kernel<<<GT, NT, smem>>>(X, W_hh, W_xh, W_hy, b_h, b_y, out);
}

// round 16
// speedup vs baseline: 1.2556x; 1.2556x over previous
#include <cuda_runtime.h>
#include <math.h>

// Problem constants
#define B    64
#define SEQ  512
#define H    1024
#define OUTD 128

// Fused config: 128 recurrence CTAs (64 col-groups x 2 batch-halves) + 20 workers.
#define G    128           // recurrence CTAs (barrier participants)
#define NEP  20            // epilogue worker CTAs (read-only pollers)
#define GT   (G + NEP)     // 148 = SM count -> all co-resident, 1 CTA/SM
#define CPC  16            // columns of W_hh per CTA
#define BPC  32            // batches per CTA
#define NT   512           // 16 warps -> 4 per SMSP
#define NW   16
#define KW   64            // k per warp (kpar halves -> 32 iters/lane)
#define NSLOT (2 * NW)     // 32 partial slots (warp x k-parity)
#define SLOT  (BPC * 18)   // 576 floats per slot: [32 b][16 j + 2 pad]

static_assert(64 * CPC == H, "col partition");
static_assert(2 * BPC == B, "batch partition");

typedef unsigned long long u64;

// Scratch (device globals: allocation-free rule). Zero-initialized at load.
__device__ float g_hs[(size_t)SEQ * H * B];  // hidden states [t][h][b]
__device__ float g_h0[H * B];                // initial h = 0 (never written)
__device__ unsigned g_arrive;
__device__ volatile unsigned g_release;

// ---------------------------------------------------------------------------
// Packed f32x2 helpers (Blackwell FFMA2)
// ---------------------------------------------------------------------------
__device__ __forceinline__ void ffma2(u64& d, u64 a, u64 b) {
    asm("fma.rn.f32x2 %0, %1, %2, %3;" : "=l"(d) : "l"(a), "l"(b), "l"(d));
}
__device__ __forceinline__ u64 dup2(float x) {
    u64 r; unsigned u = __float_as_uint(x);
    asm("mov.b64 %0, {%1, %2};" : "=l"(r) : "r"(u), "r"(u));
    return r;
}
__device__ __forceinline__ void unpack2(u64 v, float& x, float& y) {
    unsigned lo, hi;
    asm("mov.b64 {%0, %1}, %2;" : "=r"(lo), "=r"(hi) : "l"(v));
    x = __uint_as_float(lo); y = __uint_as_float(hi);
}

__device__ __forceinline__ float tanh_safe(float x) {
    float ax = fabsf(x);
    float e  = __expf(2.0f * ax);
    float r  = 1.0f - 2.0f / (e + 1.0f);
    return copysignf(r, x);
}

// ---------------------------------------------------------------------------
// Grid barrier among the 128 recurrence CTAs (proven R3/R9/R13). Workers only
// read g_release. Reset kernel zeroes state per launch (graph replays).
// ---------------------------------------------------------------------------
__device__ __forceinline__ void grid_sync() {
    __syncthreads();
    if (threadIdx.x == 0) {
        __threadfence();
        unsigned gen = g_release;
        if (atomicAdd(&g_arrive, 1u) == G - 1u) {
            g_arrive = 0;
            __threadfence();
            g_release = gen + 1u;
        } else {
            while (g_release == gen) { }
        }
        __threadfence();
    }
    __syncthreads();
}

__global__ void rnn_reset_kernel() {
    if (threadIdx.x == 0) { g_arrive = 0u; *(unsigned*)&g_release = 0u; }
}

// ---------------------------------------------------------------------------
// Fused persistent kernel.
//  bid < G : recurrence. CTA (jc = bid>>1, bc = bid&1) owns columns
//    [jc*16, jc*16+16) and batches [bc*32, bc*32+32). W slice (64 KB, natural
//    u64 j-pairs) resident in smem; per step reads h[1024][32 b] = 128 KB.
//    Warp w: k in [64w, 64w+64), kpar = lane>>4. Lane tile 4b x 16j.
//  bid >= G: epilogue worker (R13-proven body, split-k 512 threads).
// ---------------------------------------------------------------------------
__global__ void __launch_bounds__(NT, 1)
rnn_fused_kernel(const int* __restrict__ X,
                 const float* __restrict__ W_hh,
                 const float* __restrict__ W_xh,
                 const float* __restrict__ W_hy,
                 const float* __restrict__ b_h,
                 const float* __restrict__ b_y,
                 float* __restrict__ out) {
    extern __shared__ float sm[];
    const int tid = threadIdx.x;
    const int bid = blockIdx.x;

    if (bid < G) {
        // ================= recurrence role =================
        u64*   wd  = (u64*)sm;            // [H][8] W j-pairs, 64 KB
        float* red = sm + 16384;          // [32][576] partials, 72 KB

        const int jc = bid >> 1;
        const int bc = bid & 1;
        const int c0 = jc * CPC;          // column base
        const int b0 = bc * BPC;          // batch base

        // One-time W_hh slice: wd[k*8 + jp] = (W[k][c0+2jp], W[k][c0+2jp+1])
        for (int i = tid; i < H * 8; i += NT) {
            int k = i >> 3, jp = i & 7;
            wd[i] = ((const u64*)(W_hh + (size_t)k * H + c0))[jp];
        }

        const int w    = tid >> 5;
        const int lane = tid & 31;
        const int b4   = lane & 7;        // 4-batch group (0..7 -> 32 batches)
        const int jsel = (lane >> 3) & 1; // j-half: 8 cols each
        const int kpar = lane >> 4;       // k parity
        const int bb0  = b4 * 4;
        const int j0   = jsel * 8;
        const int slot = w * 2 + kpar;
        float* rst = red + slot * SLOT + bb0 * 18 + j0;  // + bi*18 + 2jp

        // Reduce mapping: 1 output/thread: jr = tid>>5 (0..15), br = tid&31
        const int jr = tid >> 5;
        const int br = tid & 31;
        const float bh = b_h[c0 + jr];

        __syncthreads();

        for (int t = 0; t < SEQ; t++) {
            const float* hp = t ? (g_hs + (size_t)(t - 1) * H * B) : g_h0;

            // Early-issue token + W_xh gather (retires under GEMM)
            int   tk = X[(b0 + br) * SEQ + t];
            float wx = W_xh[(size_t)tk * H + c0 + jr];

            u64 acc[4][4];
            #pragma unroll
            for (int bi = 0; bi < 4; bi++)
                #pragma unroll
                for (int jp = 0; jp < 4; jp++) acc[bi][jp] = 0ull;

            const int kbeg = w * KW + kpar;
            const float* hb = hp + (size_t)kbeg * B + b0 + bb0;
            const u64*   wb = wd + kbeg * 8 + jsel * 4;

            #pragma unroll 8
            for (int it = 0; it < KW / 2; it++) {
                float4 hv = *(const float4*)(hb + (size_t)it * 2 * B);
                ulonglong2 wp0 = *(const ulonglong2*)(wb + it * 16);      // jp0,jp1
                ulonglong2 wp1 = *(const ulonglong2*)(wb + it * 16 + 2);  // jp2,jp3
                u64 h0 = dup2(hv.x), h1 = dup2(hv.y), h2 = dup2(hv.z), h3 = dup2(hv.w);
                ffma2(acc[0][0], h0, wp0.x); ffma2(acc[0][1], h0, wp0.y);
                ffma2(acc[0][2], h0, wp1.x); ffma2(acc[0][3], h0, wp1.y);
                ffma2(acc[1][0], h1, wp0.x); ffma2(acc[1][1], h1, wp0.y);
                ffma2(acc[1][2], h1, wp1.x); ffma2(acc[1][3], h1, wp1.y);
                ffma2(acc[2][0], h2, wp0.x); ffma2(acc[2][1], h2, wp0.y);
                ffma2(acc[2][2], h2, wp1.x); ffma2(acc[2][3], h2, wp1.y);
                ffma2(acc[3][0], h3, wp0.x); ffma2(acc[3][1], h3, wp0.y);
                ffma2(acc[3][2], h3, wp1.x); ffma2(acc[3][3], h3, wp1.y);
            }

            // Stash: red[slot][b][j] (u64 stores; offsets even -> aligned)
            #pragma unroll
            for (int bi = 0; bi < 4; bi++) {
                u64* rb = (u64*)(rst + bi * 18);
                rb[0] = acc[bi][0]; rb[1] = acc[bi][1];
                rb[2] = acc[bi][2]; rb[3] = acc[bi][3];
            }
            __syncthreads();

            // Reduce 32 slots + input proj + bias + tanh; write h_t [h][b].
            {
                const float* rb = red + br * 18 + jr;
                float s0 = 0.f, s1 = 0.f, s2 = 0.f, s3 = 0.f;
                #pragma unroll
                for (int sl = 0; sl < NSLOT; sl += 4) {
                    s0 += rb[(sl + 0) * SLOT];
                    s1 += rb[(sl + 1) * SLOT];
                    s2 += rb[(sl + 2) * SLOT];
                    s3 += rb[(sl + 3) * SLOT];
                }
                float x = ((s0 + s1) + (s2 + s3)) + wx + bh;
                g_hs[(size_t)t * H * B + (size_t)(c0 + jr) * B + b0 + br] = tanh_safe(x);
            }

            grid_sync();
        }
    } else {
        // ================= epilogue worker role (R13 verbatim) =================
        float* hc = sm;             // [k64][b64]  16 KB
        float* Wc = sm + 64 * 64;   // [k64][o128] 32 KB

        const int tl = tid & 255;          // tile lane: pair (tl, tl+256)
        const int eb0 = (tl & 15) * 4;
        const int o0  = (tl >> 4) * 8;
        const int kh  = (tid >> 8) * 32;   // k-half: 0 or 32

        float byv[8];
        #pragma unroll
        for (int oi = 0; oi < 8; oi++) byv[oi] = b_y[o0 + oi];

        for (int t = bid - G; t < SEQ; t += NEP) {
            if (tid == 0) {
                while (g_release < (unsigned)(t + 1)) __nanosleep(128);
                __threadfence();
            }
            __syncthreads();

            u64 acc[4][4];
            #pragma unroll
            for (int bi = 0; bi < 4; bi++)
                #pragma unroll
                for (int op = 0; op < 4; op++) acc[bi][op] = 0ull;

            const float* hsrc = g_hs + (size_t)t * H * B;

            for (int k0 = 0; k0 < H; k0 += 64) {
                const float4* hsv = (const float4*)(hsrc + (size_t)k0 * B);
                float4* hcv = (float4*)hc;
                #pragma unroll
                for (int i = 0; i < 2; i++) hcv[tid + i * 512] = hsv[tid + i * 512];

                const float4* wsv = (const float4*)(W_hy + (size_t)k0 * OUTD);
                float4* wcv = (float4*)Wc;
                #pragma unroll
                for (int i = 0; i < 4; i++) wcv[tid + i * 512] = wsv[tid + i * 512];

                __syncthreads();

                #pragma unroll 4
                for (int kk = 0; kk < 32; kk++) {
                    int k = kh + kk;
                    float4 hv = *(const float4*)(hc + k * 64 + eb0);
                    ulonglong2 wq0 = *(const ulonglong2*)(Wc + k * OUTD + o0);
                    ulonglong2 wq1 = *(const ulonglong2*)(Wc + k * OUTD + o0 + 4);
                    u64 h0 = dup2(hv.x), h1 = dup2(hv.y), h2 = dup2(hv.z), h3 = dup2(hv.w);
                    ffma2(acc[0][0], h0, wq0.x); ffma2(acc[0][1], h0, wq0.y);
                    ffma2(acc[0][2], h0, wq1.x); ffma2(acc[0][3], h0, wq1.y);
                    ffma2(acc[1][0], h1, wq0.x); ffma2(acc[1][1], h1, wq0.y);
                    ffma2(acc[1][2], h1, wq1.x); ffma2(acc[1][3], h1, wq1.y);
                    ffma2(acc[2][0], h2, wq0.x); ffma2(acc[2][1], h2, wq0.y);
                    ffma2(acc[2][2], h2, wq1.x); ffma2(acc[2][3], h2, wq1.y);
                    ffma2(acc[3][0], h3, wq0.x); ffma2(acc[3][1], h3, wq0.y);
                    ffma2(acc[3][2], h3, wq1.x); ffma2(acc[3][3], h3, wq1.y);
                }
                __syncthreads();
            }

            {
                float* stage = hc;
                if (tid >= 256) {
                    float* dstp = stage + tl * 33;
                    #pragma unroll
                    for (int bi = 0; bi < 4; bi++) {
                        float f[8];
                        unpack2(acc[bi][0], f[0], f[1]);
                        unpack2(acc[bi][1], f[2], f[3]);
                        unpack2(acc[bi][2], f[4], f[5]);
                        unpack2(acc[bi][3], f[6], f[7]);
                        #pragma unroll
                        for (int oi = 0; oi < 8; oi++) dstp[bi * 8 + oi] = f[oi];
                    }
                }
                __syncthreads();
                if (tid < 256) {
                    const float* srcp = stage + tl * 33;
                    #pragma unroll
                    for (int bi = 0; bi < 4; bi++) {
                        float f[8];
                        unpack2(acc[bi][0], f[0], f[1]);
                        unpack2(acc[bi][1], f[2], f[3]);
                        unpack2(acc[bi][2], f[4], f[5]);
                        unpack2(acc[bi][3], f[6], f[7]);
                        float* dst = out + ((size_t)(eb0 + bi) * SEQ + t) * OUTD + o0;
                        float4 v0, v1;
                        v0.x = f[0] + srcp[bi*8+0] + byv[0];
                        v0.y = f[1] + srcp[bi*8+1] + byv[1];
                        v0.z = f[2] + srcp[bi*8+2] + byv[2];
                        v0.w = f[3] + srcp[bi*8+3] + byv[3];
                        v1.x = f[4] + srcp[bi*8+4] + byv[4];
                        v1.y = f[5] + srcp[bi*8+5] + byv[5];
                        v1.z = f[6] + srcp[bi*8+6] + byv[6];
                        v1.w = f[7] + srcp[bi*8+7] + byv[7];
                        *(float4*)(dst)     = v0;
                        *(float4*)(dst + 4) = v1;
                    }
                }
                __syncthreads();
            }
        }
    }
}

// ---------------------------------------------------------------------------
// Launch. Inputs: X[i32 64x512], W_hh[f32 1024x1024], W_xh[f32 128x1024],
// W_hy[f32 1024x128], b_h[1024], b_y[128]. Output: f32 [64][512][128].
// ---------------------------------------------------------------------------
extern "C" void kernel_launch(void* const* d_in, const int* in_sizes, int n_in,
                              void* d_out, int out_size) {
    const int*   X    = (const int*)  d_in[0];
    const float* W_hh = (const float*)d_in[1];
    const float* W_xh = (const float*)d_in[2];
    const float* W_hy = (const float*)d_in[3];
    const float* b_h  = (const float*)d_in[4];
    const float* b_y  = (const float*)d_in[5];
    float* out = (float*)d_out;

    const int smem_rec = (16384 + NSLOT * SLOT) * (int)sizeof(float);  // 64+72 KB
    const int smem_epi = (64 * 64 + 64 * OUTD) * (int)sizeof(float);
    const int smem = smem_rec > smem_epi ? smem_rec : smem_epi;

    cudaFuncSetAttribute(rnn_fused_kernel,
                         cudaFuncAttributeMaxDynamicSharedMemorySize, smem);

    rnn_reset_kernel<<<1, 32>>>();
    rnn_fused_kernel<<<GT, NT, smem>>>(X, W_hh, W_xh, W_hy, b_h, b_y, out);
}